// round 6
// baseline (speedup 1.0000x reference)
#include <cuda_runtime.h>
#include <cstring>

#define B_N 65536
#define D_N 1024
#define TILES 2048          // B_N / 32 rows per tile
#define NBLOCKS 152         // GB300: 152 SMs, 1 CTA/SM (smem-limited)

// ---------------- device scratch (no runtime allocation allowed) ----------------
__device__ float2 g_Wp[16 * 1024];   // folded, swizzled W_eff: [pair p][s], cols (2p,2p+1)
__device__ float  g_zw[32];          // m_z[g] * W_zg[h]  at [g*8+h]

struct MainParams {
    const float* x;
    const float* hp;
    const float* cp;
    const float* zp;
    const float* Wh0; const float* Wh1; const float* Wh2; const float* Wh3;
    const float* b0;  const float* b1;  const float* b2;  const float* b3;
    const float* Wd1; const float* bd1;
    const float* Wd2; const float* bd2;
    const float* Wd3; const float* bd3;
    const float* m1;  const float* m2;
    float* out;
};

struct Smem {
    float2 Wp[16][1024];    // 128 KB  folded input weights (swizzled over d)
    float  gate[4][8][32];  // [rowgroup][row][j = g*8+h] pre-activations (x-part)
    float  ht[32][8];
    float  wh[4][64];       // [g][k*8+h]
    float  zw[32];
    float  bias[32];
};

// ---------------- packed f32x2 helpers ----------------
__device__ __forceinline__ unsigned long long pk2(float v) {
    unsigned long long r;
    asm("mov.b64 %0, {%1, %2};" : "=l"(r) : "f"(v), "f"(v));
    return r;
}
__device__ __forceinline__ void fma2(unsigned long long& d, unsigned long long a, unsigned long long b) {
    asm("fma.rn.f32x2 %0, %1, %2, %0;" : "+l"(d) : "l"(a), "l"(b));
}
__device__ __forceinline__ void unpk(unsigned long long v, float& lo, float& hi) {
    asm("mov.b64 {%0, %1}, %2;" : "=f"(lo), "=f"(hi) : "l"(v));
}
__device__ __forceinline__ float hsig(float x) {
    return fminf(fmaxf(fmaf(x, 0.16666667f, 0.5f), 0.0f), 1.0f);
}

// ---------------- prep: fold dropout mask into weights, swizzle over d ----------------
__global__ void prep_kernel(const float* Wxi, const float* Wxf, const float* Wxc, const float* Wxo,
                            const float* mx,
                            const float* Wzi, const float* Wzf, const float* Wzc, const float* Wzo,
                            const float* mz) {
    int idx = blockIdx.x * 256 + threadIdx.x;     // 0 .. 32767 : (d, j)
    int d = idx >> 5;
    int j = idx & 31;
    int g = j >> 3;
    int h = j & 7;
    const float* Wx = (g == 0) ? Wxi : (g == 1) ? Wxf : (g == 2) ? Wxc : Wxo;
    float val = Wx[d * 8 + h] * mx[g * D_N + d];
    int p = j >> 1;
    int s = ((d & 3) << 8) | (d >> 2);            // swizzle so lane-stride-1 smem reads
    reinterpret_cast<float*>(g_Wp)[((p << 10) + s) * 2 + (j & 1)] = val;

    if (idx < 32) {
        int gg = idx >> 3; int hh = idx & 7;
        const float* Wz = (gg == 0) ? Wzi : (gg == 1) ? Wzf : (gg == 2) ? Wzc : Wzo;
        g_zw[idx] = mz[gg] * Wz[hh];
    }
}

// ---------------- main fused kernel ----------------
__global__ __launch_bounds__(256, 1)
void lstm_main(MainParams P) {
    extern __shared__ char raw[];
    Smem& S = *reinterpret_cast<Smem*>(raw);
    int t = threadIdx.x;

    // Fill smem W (once per CTA; persistent grid -> once per SM)
    {
        const float4* src = reinterpret_cast<const float4*>(g_Wp);
        float4* dst = reinterpret_cast<float4*>(S.Wp);
        #pragma unroll
        for (int i = 0; i < 32; i++)              // 8192 float4 / 256 threads
            dst[t + i * 256] = src[t + i * 256];
    }
    {
        int g = t >> 6, rem = t & 63;
        const float* W = (g == 0) ? P.Wh0 : (g == 1) ? P.Wh1 : (g == 2) ? P.Wh2 : P.Wh3;
        S.wh[g][rem] = W[rem];
    }
    if (t < 32) {
        S.zw[t] = g_zw[t];
        int g = t >> 3; int h = t & 7;
        const float* b = (g == 0) ? P.b0 : (g == 1) ? P.b1 : (g == 2) ? P.b2 : P.b3;
        S.bias[t] = b[h];
    }
    __syncthreads();

    int w = t >> 5, lane = t & 31;
    int gp = w & 1;          // gate pair: 0 -> cols 0..15 (I,F), 1 -> cols 16..31 (C,O)
    int rg = w >> 1;         // row group 0..3 (8 rows each)

    for (int tile = blockIdx.x; tile < TILES; tile += gridDim.x) {
        int base_row = tile * 32;
        int row0 = base_row + rg * 8;

        unsigned long long acc[8][8];             // [row][col-pair] packed f32x2
        #pragma unroll
        for (int r = 0; r < 8; r++)
            #pragma unroll
            for (int p = 0; p < 8; p++) acc[r][p] = 0ull;

        const float* xbase = P.x + (size_t)row0 * D_N + lane * 4;
        for (int c = 0; c < 8; c++) {
            float4 xv[8];
            #pragma unroll
            for (int r = 0; r < 8; r++)
                xv[r] = *reinterpret_cast<const float4*>(xbase + (size_t)r * D_N + c * 128);
            #pragma unroll
            for (int dd = 0; dd < 4; dd++) {
                int s = dd * 256 + c * 32 + lane;     // conflict-free (lane stride 1)
                unsigned long long wv[8];
                #pragma unroll
                for (int p = 0; p < 8; p++)
                    wv[p] = *reinterpret_cast<const unsigned long long*>(&S.Wp[gp * 8 + p][s]);
                #pragma unroll
                for (int r = 0; r < 8; r++) {
                    float xs = (dd == 0) ? xv[r].x : (dd == 1) ? xv[r].y : (dd == 2) ? xv[r].z : xv[r].w;
                    unsigned long long a = pk2(xs);
                    #pragma unroll
                    for (int p = 0; p < 8; p++)
                        fma2(acc[r][p], a, wv[p]);    // 2 FMAs/inst
                }
            }
        }

        // cross-lane reduction (each lane covered a distinct d-subset)
        #pragma unroll
        for (int r = 0; r < 8; r++) {
            #pragma unroll
            for (int p = 0; p < 8; p++) {
                float lo, hi;
                unpk(acc[r][p], lo, hi);
                #pragma unroll
                for (int off = 16; off > 0; off >>= 1) {
                    lo += __shfl_xor_sync(0xffffffffu, lo, off);
                    hi += __shfl_xor_sync(0xffffffffu, hi, off);
                }
                if (lane == r) {
                    S.gate[rg][r][gp * 16 + 2 * p]     = lo;
                    S.gate[rg][r][gp * 16 + 2 * p + 1] = hi;
                }
            }
        }
        __syncthreads();

        // gate epilogue: one thread per (row, h)
        {
            int rr = t >> 3, h = t & 7;
            int erg = rr >> 3, er = rr & 7;
            int row = base_row + rr;
            float hv[8];
            *reinterpret_cast<float4*>(hv)     = *reinterpret_cast<const float4*>(P.hp + (size_t)row * 8);
            *reinterpret_cast<float4*>(hv + 4) = *reinterpret_cast<const float4*>(P.hp + (size_t)row * 8 + 4);
            float zv = P.zp[row];
            float pre[4];
            #pragma unroll
            for (int g = 0; g < 4; g++) {
                float s = S.gate[erg][er][g * 8 + h] + S.bias[g * 8 + h];
                s = fmaf(zv, S.zw[g * 8 + h], s);
                #pragma unroll
                for (int k = 0; k < 8; k++)
                    s = fmaf(hv[k], S.wh[g][k * 8 + h], s);
                pre[g] = s;
            }
            float It = hsig(pre[0]);
            float Ft = hsig(pre[1]);
            float ct = Ft * P.cp[(size_t)row * 8 + h] + It * tanhf(pre[2]);
            float ht = hsig(pre[3]) * tanhf(ct);
            P.out[(size_t)B_N + (size_t)row * 8 + h]     = ht;   // ht block
            P.out[(size_t)9 * B_N + (size_t)row * 8 + h] = ct;   // ct block
            S.ht[rr][h] = ht;
        }
        __syncthreads();

        // dense head + zt: one thread per row (32 rows)
        if (t < 32) {
            int row = base_row + t;
            float hv[8];
            #pragma unroll
            for (int k = 0; k < 8; k++) hv[k] = S.ht[t][k];
            float d1[5], d2[5];
            #pragma unroll
            for (int wj = 0; wj < 5; wj++) {
                float s = P.bd1[wj];
                #pragma unroll
                for (int k = 0; k < 8; k++) s = fmaf(hv[k], P.Wd1[k * 5 + wj], s);
                d1[wj] = fmaxf(s, 0.0f) * P.m1[wj];
            }
            #pragma unroll
            for (int wj = 0; wj < 5; wj++) {
                float s = P.bd2[wj];
                #pragma unroll
                for (int k = 0; k < 5; k++) s = fmaf(d1[k], P.Wd2[k * 5 + wj], s);
                d2[wj] = fmaxf(s, 0.0f) * P.m2[wj];
            }
            float s = P.bd3[0];
            #pragma unroll
            for (int k = 0; k < 5; k++) s = fmaf(d2[k], P.Wd3[k], s);
            P.out[row] = P.zp[row] + fmaxf(s, 0.0f);             // zt block
        }
        // no trailing sync needed: next tile's smem writes are ordered by the syncs above
    }
}

// ---------------- launch ----------------
extern "C" void kernel_launch(void* const* d_in, const int* in_sizes, int n_in,
                              void* d_out, int out_size) {
    (void)in_sizes; (void)n_in; (void)out_size;
    const float* x   = (const float*)d_in[0];
    const float* hp  = (const float*)d_in[1];
    const float* cp  = (const float*)d_in[2];
    const float* zp  = (const float*)d_in[3];
    const float* Wxi = (const float*)d_in[4];
    const float* Wxf = (const float*)d_in[5];
    const float* Wxc = (const float*)d_in[6];
    const float* Wxo = (const float*)d_in[7];
    const float* Whi = (const float*)d_in[8];
    const float* Whf = (const float*)d_in[9];
    const float* Whc = (const float*)d_in[10];
    const float* Who = (const float*)d_in[11];
    const float* Wzi = (const float*)d_in[12];
    const float* Wzf = (const float*)d_in[13];
    const float* Wzc = (const float*)d_in[14];
    const float* Wzo = (const float*)d_in[15];
    const float* b_i = (const float*)d_in[16];
    const float* b_f = (const float*)d_in[17];
    const float* b_c = (const float*)d_in[18];
    const float* b_o = (const float*)d_in[19];
    const float* Wd1 = (const float*)d_in[20];
    const float* bd1 = (const float*)d_in[21];
    const float* Wd2 = (const float*)d_in[22];
    const float* bd2 = (const float*)d_in[23];
    const float* Wd3 = (const float*)d_in[24];
    const float* bd3 = (const float*)d_in[25];
    const float* m_x = (const float*)d_in[26];
    const float* m_z = (const float*)d_in[27];
    const float* m_1 = (const float*)d_in[28];
    const float* m_2 = (const float*)d_in[29];
    float* out = (float*)d_out;

    prep_kernel<<<128, 256>>>(Wxi, Wxf, Wxc, Wxo, m_x, Wzi, Wzf, Wzc, Wzo, m_z);

    MainParams P;
    P.x = x; P.hp = hp; P.cp = cp; P.zp = zp;
    P.Wh0 = Whi; P.Wh1 = Whf; P.Wh2 = Whc; P.Wh3 = Who;
    P.b0 = b_i; P.b1 = b_f; P.b2 = b_c; P.b3 = b_o;
    P.Wd1 = Wd1; P.bd1 = bd1; P.Wd2 = Wd2; P.bd2 = bd2; P.Wd3 = Wd3; P.bd3 = bd3;
    P.m1 = m_1; P.m2 = m_2;
    P.out = out;

    cudaFuncSetAttribute((const void*)lstm_main,
                         cudaFuncAttributeMaxDynamicSharedMemorySize,
                         (int)sizeof(Smem));
    lstm_main<<<NBLOCKS, 256, sizeof(Smem)>>>(P);
}